// round 15
// baseline (speedup 1.0000x reference)
#include <cuda_runtime.h>

// Problem constants (fixed by setup_inputs): B=4, N=M=8192, D=3
constexpr int Bn   = 4;
constexpr int Np   = 8192;
constexpr int NPTS = 2 * Bn * Np;   // 65536 queries total (both directions)
constexpr int GD   = 30;            // grid cells per axis
constexpr int NC   = GD * GD * GD;  // 27000 cells per (cloud,batch)
constexpr int NSEG = 2 * Bn;        // 8 segments: cloud (src/tgt) x batch
constexpr int NCELLS = NSEG * NC;   // 216000
constexpr float HLO  = -6.0f;       // grid domain [-6, 6]
constexpr float H    = 0.4f;        // cell size
constexpr float INVH = 2.5f;
constexpr float BOUND2 = H * H;     // 3^3 neighborhood exactness bound (0.16)

// Scratch (static __device__, no allocs). All state rewritten every call.
__device__ int    g_cnt [NCELLS];
__device__ int2   g_cell[NCELLS];    // (start, count)
__device__ int    g_cur [NCELLS];
__device__ float4 g_pts [NSEG * Np]; // cell-sorted points, .w = |p|^2
__device__ int    g_idx [NSEG * Np]; // original index of sorted point
__device__ float  g_mind[NPTS];      // min d2 per (dir, batch, ORIGINAL idx)
__device__ int    g_fq  [NPTS];      // unresolved query slots (into g_pts)
__device__ int    g_fcnt;

__device__ __forceinline__ int cellof(float v) {
    int c = __float2int_rd((v - HLO) * INVH);
    return min(max(c, 0), GD - 1);
}
__device__ __forceinline__ unsigned redux_min(unsigned v) {
    unsigned d;
    asm("redux.sync.min.u32 %0, %1, 0xffffffff;" : "=r"(d) : "r"(v));
    return d;
}

// ---- build stage ----

__global__ void zero_cnt() {
    int i = blockIdx.x * blockDim.x + threadIdx.x;
    if (i < NCELLS) g_cnt[i] = 0;
    if (i == 0) g_fcnt = 0;
}

__global__ void count_pts(const float* __restrict__ src, const float* __restrict__ tgt) {
    int t  = blockIdx.x * blockDim.x + threadIdx.x;  // 65536
    int c  = t >> 15;            // cloud: 0=src, 1=tgt
    int rr = t & 32767;          // b*8192 + i
    const float* p = (c ? tgt : src) + (size_t)rr * 3;
    int ci = (cellof(p[2]) * GD + cellof(p[1])) * GD + cellof(p[0]);
    int seg = c * Bn + (rr >> 13);
    atomicAdd(&g_cnt[seg * NC + ci], 1);
}

// One block per segment: serial chunk sums + Hillis-Steele scan of 1024 partials.
__global__ void scan_cells() {
    __shared__ int sh[1024];
    constexpr int CH = (NC + 1023) / 1024;  // 27
    const int tid  = threadIdx.x;
    const int base = blockIdx.x * NC;
    int s = 0;
    for (int k = 0; k < CH; k++) {
        int idx = tid * CH + k;
        if (idx < NC) s += g_cnt[base + idx];
    }
    sh[tid] = s;
    __syncthreads();
    int v = s;
    for (int off = 1; off < 1024; off <<= 1) {
        int u = (tid >= off) ? sh[tid - off] : 0;
        __syncthreads();
        v += u;
        sh[tid] = v;
        __syncthreads();
    }
    int run = v - s;  // exclusive prefix of this thread's chunk
    for (int k = 0; k < CH; k++) {
        int idx = tid * CH + k;
        if (idx < NC) {
            int c = g_cnt[base + idx];
            g_cell[base + idx] = make_int2(run, c);
            g_cur[base + idx]  = run;
            run += c;
        }
    }
}

__global__ void scatter_pts(const float* __restrict__ src, const float* __restrict__ tgt) {
    int t  = blockIdx.x * blockDim.x + threadIdx.x;
    int c  = t >> 15;
    int rr = t & 32767;
    const float* p = (c ? tgt : src) + (size_t)rr * 3;
    float x = p[0], y = p[1], z = p[2];
    int ci  = (cellof(z) * GD + cellof(y)) * GD + cellof(x);
    int seg = c * Bn + (rr >> 13);
    int slot = atomicAdd(&g_cur[seg * NC + ci], 1);  // order-nondet, set-min invariant
    g_pts[seg * Np + slot] = make_float4(x, y, z, fmaf(x, x, fmaf(y, y, z * z)));
    g_idx[seg * Np + slot] = rr & 8191;
}

// ---- phase 1: per-CELL uniform neighborhood scan ----
// One warp per (segment, cell). All queries in a cell share the SAME 27-cell
// database neighborhood: candidates are streamed with uniform-address broadcast
// LDGs (1 wavefront), zero divergence -- brute-force shape, ~400 candidates.

__global__ void __launch_bounds__(256)
nn_cells() {
    const int lane = threadIdx.x & 31;
    const int gw   = (blockIdx.x * blockDim.x + threadIdx.x) >> 5;
    const int NW   = (gridDim.x * blockDim.x) >> 5;

    for (int ci = gw; ci < NCELLS; ci += NW) {
        int2 qc = g_cell[ci];
        if (qc.y == 0) continue;
        const int seg  = ci / NC;
        const int cell = ci - seg * NC;
        const int dseg = seg ^ Bn;          // flip cloud, keep batch
        const int qpb  = seg * Np;
        const int ppb  = dseg * Np;
        const int dcb  = dseg * NC;
        const int cz = cell / (GD * GD);
        const int rem = cell - cz * GD * GD;
        const int cy = rem / GD;
        const int cx = rem - cy * GD;
        const int xlo = max(cx - 1, 0), xhi = min(cx + 1, GD - 1);
        const int zlo = max(cz - 1, 0), zhi = min(cz + 1, GD - 1);
        const int ylo = max(cy - 1, 0), yhi = min(cy + 1, GD - 1);
        const int d = seg >> 2;   // direction = query cloud
        const int b = seg & (Bn - 1);

        for (int q0 = 0; q0 < qc.y; q0 += 32) {
            int qi = q0 + lane;
            bool valid = qi < qc.y;
            float4 q = g_pts[qpb + qc.x + min(qi, qc.y - 1)];  // coalesced
            float qx2 = -2.0f * q.x, qy2 = -2.0f * q.y, qz2 = -2.0f * q.z;

            float emin = 3.4e38f;
            for (int z = zlo; z <= zhi; z++) {
                for (int y = ylo; y <= yhi; y++) {
                    int rowb = dcb + (z * GD + y) * GD;
                    int2 c0 = g_cell[rowb + xlo];
                    int2 c1 = g_cell[rowb + xhi];
                    int e = c1.x + c1.y;   // contiguous range (counting sort)
#pragma unroll 4
                    for (int u = c0.x; u < e; u++) {
                        float4 c = g_pts[ppb + u];   // uniform addr: broadcast LDG
                        // e = |c|^2 - 2 q.c  (3 FFMA; min d2 = |q|^2 + emin)
                        float t = fmaf(qx2, c.x,
                                  fmaf(qy2, c.y,
                                  fmaf(qz2, c.z, c.w)));
                        emin = fminf(emin, t);
                    }
                }
            }
            float best = q.w + emin;  // d2 (same expansion form as reference)
            if (valid) {
                if (best <= BOUND2) {
                    g_mind[d * (Bn * Np) + b * Np + g_idx[qpb + qc.x + qi]] = best;
                } else {
                    g_fq[atomicAdd(&g_fcnt, 1)] = qpb + qc.x + qi;  // slot token
                }
            }
        }
    }
}

// ---- phase 2: one warp per unresolved query, full coalesced scan ----

__global__ void __launch_bounds__(256)
nn_far() {
    const int lane = threadIdx.x & 31;
    const int wid  = (blockIdx.x * blockDim.x + threadIdx.x) >> 5;  // 2048 warps
    const int nf   = g_fcnt;
    for (int fi = wid; fi < nf; fi += 2048) {
        int slot = g_fq[fi];
        int seg  = slot / Np;
        int d = seg >> 2, b = seg & (Bn - 1);
        float4 q = g_pts[slot];
        const int pbase = (seg ^ Bn) * Np;

        float qx2 = -2.0f * q.x, qy2 = -2.0f * q.y, qz2 = -2.0f * q.z;
        float emin = 3.4e38f;
        for (int i = lane; i < Np; i += 32) {   // coalesced LDG.128 scan
            float4 tp = g_pts[pbase + i];
            float t = fmaf(qx2, tp.x, fmaf(qy2, tp.y, fmaf(qz2, tp.z, tp.w)));
            emin = fminf(emin, t);
        }
        float best = q.w + emin;
        // clamp tiny negative artifacts so raw bits order as uint
        unsigned m = redux_min(__float_as_uint(fmaxf(best, 0.0f)));
        if (lane == 0)
            g_mind[d * (Bn * Np) + b * Np + g_idx[slot]] = __uint_as_float(m);
    }
}

// ---- deterministic fixed-order sum ----

__global__ void final_sum(float* out) {
    __shared__ float sh[1024];
    int tid = threadIdx.x;
    float s = 0.0f;
    for (int i = tid; i < NPTS; i += 1024) s += g_mind[i];  // fixed order
    sh[tid] = s;
    __syncthreads();
#pragma unroll
    for (int st = 512; st > 0; st >>= 1) {
        if (tid < st) sh[tid] += sh[tid + st];
        __syncthreads();
    }
    if (tid == 0)
        out[0] = sh[0] / (float)(Bn * Np);  // (sum_fwd + sum_bwd) / (B*G)
}

extern "C" void kernel_launch(void* const* d_in, const int* in_sizes, int n_in,
                              void* d_out, int out_size) {
    const float* src = (const float*)d_in[0];  // (4, 8192, 3) fp32
    const float* tgt = (const float*)d_in[1];  // (4, 8192, 3) fp32
    float* out = (float*)d_out;

    zero_cnt<<<(NCELLS + 1023) / 1024, 1024>>>();
    count_pts<<<NPTS / 256, 256>>>(src, tgt);
    scan_cells<<<NSEG, 1024>>>();
    scatter_pts<<<NPTS / 256, 256>>>(src, tgt);
    nn_cells<<<512, 256>>>();
    nn_far<<<256, 256>>>();
    final_sum<<<1, 1024>>>(out);
}